// round 13
// baseline (speedup 1.0000x reference)
#include <cuda_runtime.h>
#include <cuda_fp16.h>
#include <cstdint>
#include <cstddef>

// Problem constants
constexpr int Bc  = 2;
constexpr int Sc  = 2048;
constexpr int HS  = 2048;
constexpr int NHc = 16;
constexpr int HDc = 128;
constexpr int MR  = Bc * Sc;    // 4096 rows of (b, s)
constexpr int BHc = Bc * NHc;   // 32 (batch*heads)
constexpr float SCALE = 0.08838834764831845f;  // 1/sqrt(128)

// Scratch (device globals — allocation-free per harness rules)
__device__ __half g_q [MR * HS];
__device__ __half g_k [MR * HS];
__device__ __half g_v [MR * HS];
__device__ __half g_ao[MR * HS];
__device__ __half g_hs[MR * HS];
__device__ __half g_wq[HS * HS];
__device__ __half g_wk[HS * HS];
__device__ __half g_wv[HS * HS];
__device__ __half g_wo[HS * HS];

// ---------------------------------------------------------------------------
// Helpers
// ---------------------------------------------------------------------------
__device__ __forceinline__ uint32_t smem_u32(const void* p) {
    uint32_t a;
    asm("{ .reg .u64 t; cvta.to.shared.u64 t, %1; cvt.u32.u64 %0, t; }"
        : "=r"(a) : "l"(p));
    return a;
}
__device__ __forceinline__ void cpa16(uint32_t dst, const void* src) {
    asm volatile("cp.async.cg.shared.global [%0], [%1], 16;"
                 :: "r"(dst), "l"(src) : "memory");
}
__device__ __forceinline__ void cpa_commit() {
    asm volatile("cp.async.commit_group;" ::: "memory");
}
template <int N>
__device__ __forceinline__ void cpa_wait() {
    asm volatile("cp.async.wait_group %0;" :: "n"(N) : "memory");
}
__device__ __forceinline__ void ldsm4(uint32_t* r, uint32_t a) {
    asm volatile("ldmatrix.sync.aligned.m8n8.x4.shared.b16 {%0,%1,%2,%3}, [%4];"
                 : "=r"(r[0]), "=r"(r[1]), "=r"(r[2]), "=r"(r[3]) : "r"(a));
}
__device__ __forceinline__ void ldsm4t(uint32_t* r, uint32_t a) {
    asm volatile("ldmatrix.sync.aligned.m8n8.x4.trans.shared.b16 {%0,%1,%2,%3}, [%4];"
                 : "=r"(r[0]), "=r"(r[1]), "=r"(r[2]), "=r"(r[3]) : "r"(a));
}
__device__ __forceinline__ void mma16(float* c, const uint32_t* a, const uint32_t* b) {
    asm volatile(
        "mma.sync.aligned.m16n8k16.row.col.f32.f16.f16.f32 "
        "{%0,%1,%2,%3},{%4,%5,%6,%7},{%8,%9},{%0,%1,%2,%3};\n"
        : "+f"(c[0]), "+f"(c[1]), "+f"(c[2]), "+f"(c[3])
        : "r"(a[0]), "r"(a[1]), "r"(a[2]), "r"(a[3]),
          "r"(b[0]), "r"(b[1]));
}
__device__ __forceinline__ uint32_t packh2(float a, float b) {
    __half2 h = __floats2half2_rn(a, b);
    return *(uint32_t*)&h;
}

// ---------------------------------------------------------------------------
// Merged fp16 conversion, 4 float4 per thread (MLP=4).
// grid = (2048, 5). y=0: hs (n4=2M uses all blocks); y=1..4: weights (n4=1M).
// ---------------------------------------------------------------------------
__global__ __launch_bounds__(256) void round_all(
    const float4* __restrict__ hs, const float4* __restrict__ w0,
    const float4* __restrict__ w1, const float4* __restrict__ w2,
    const float4* __restrict__ w3,
    uint2* __restrict__ ohs, uint2* __restrict__ o0, uint2* __restrict__ o1,
    uint2* __restrict__ o2, uint2* __restrict__ o3)
{
    const int y = blockIdx.y;
    const float4* in  = (y == 0) ? hs : (y == 1) ? w0 : (y == 2) ? w1
                      : (y == 3) ? w2 : w3;
    uint2*        out = (y == 0) ? ohs : (y == 1) ? o0 : (y == 2) ? o1
                      : (y == 3) ? o2 : o3;
    const int n4 = (y == 0) ? (MR * HS / 4) : (HS * HS / 4);
    const int base = blockIdx.x * 1024 + threadIdx.x;
    if (base >= n4) return;

    float4 v[4];
    int   idx[4];
    int   cnt = 0;
#pragma unroll
    for (int i = 0; i < 4; i++) {
        int j = base + i * 256;
        if (j < n4) { idx[cnt] = j; v[cnt] = in[j]; cnt++; }
    }
#pragma unroll
    for (int i = 0; i < 4; i++) {
        if (i < cnt) {
            uint2 o;
            o.x = packh2(v[i].x, v[i].y);
            o.y = packh2(v[i].z, v[i].w);
            out[idx[i]] = o;
        }
    }
}

// ---------------------------------------------------------------------------
// fp16 TN GEMM: C[M,N] = A[M,K] * B[N,K]^T
// Block tile 128x128, 4 warps (2x2) of 64x64, BK=64 halves, 128 threads.
// 3-stage cp.async ring (32KB/stage = 96KB) -> 2 CTAs/SM.
// NEW: next-stage cp.async issue is SPREAD across the ks-groups (A-half after
// ks=0, B-half after ks=2) so LDGSTS issue overlaps HMMA execution.
// Optional fused RoPE epilogue (doRope).
// ---------------------------------------------------------------------------
constexpr int GB_N      = 128;
constexpr int GH_A      = 128 * 128;          // bytes per operand per stage
constexpr int GH_STAGE  = 2 * GH_A;           // 32768
constexpr int GH_SMEM   = 3 * GH_STAGE;       // 98304
constexpr int RT_STRIDE = 68;                 // h2 per staged row (64 + pad)

template <bool OUTF>
__device__ __forceinline__ void gemm_body(
    const __half* __restrict__ A, const __half* __restrict__ B,
    void* __restrict__ Cv, int lda, int ldb, int ldc, int K, char* dsm,
    const float* __restrict__ cb, const float* __restrict__ sb, bool doRope)
{
    const uint32_t sbase = smem_u32(dsm);
    const int tid  = threadIdx.x;               // 0..127
    const int lane = tid & 31, warp = tid >> 5; // warp 0..3
    const int g = lane >> 2, tg = lane & 3;
    const int wm = (warp >> 1) * 64;            // 0 or 64
    const int wn = (warp & 1) * 64;             // 0 or 64

    const __half* Ab = A + (size_t)blockIdx.y * 128 * lda;
    const __half* Bb = B + (size_t)blockIdx.x * GB_N * ldb;

    float acc[4][8][4];
#pragma unroll
    for (int mi = 0; mi < 4; mi++)
#pragma unroll
        for (int ni = 0; ni < 8; ni++)
#pragma unroll
            for (int j = 0; j < 4; j++) acc[mi][ni][j] = 0.f;

    // Full-stage issue (prologue only)
    auto issue = [&](int s, int k0) {
        const uint32_t stA = sbase + s * GH_STAGE;
        const uint32_t stB = stA + GH_A;
#pragma unroll
        for (int i = 0; i < 8; i++) {
            int idx = tid + i * 128;
            int r = idx >> 3, u = idx & 7;
            cpa16(stA + r * 128 + ((u ^ (r & 7)) << 4),
                  Ab + (size_t)r * lda + k0 + u * 8);
        }
#pragma unroll
        for (int i = 0; i < 8; i++) {
            int idx = tid + i * 128;
            int r = idx >> 3, u = idx & 7;
            cpa16(stB + r * 128 + ((u ^ (r & 7)) << 4),
                  Bb + (size_t)r * ldb + k0 + u * 8);
        }
        cpa_commit();
    };

    // Half-stage issue (spread in mainloop): which==0 -> A, which==1 -> B
    auto issue_half = [&](int s, int k0, int which) {
        const uint32_t st = sbase + s * GH_STAGE + which * GH_A;
        const __half* src = which ? Bb : Ab;
        const int ld = which ? ldb : lda;
#pragma unroll
        for (int i = 0; i < 8; i++) {
            int idx = tid + i * 128;
            int r = idx >> 3, u = idx & 7;
            cpa16(st + r * 128 + ((u ^ (r & 7)) << 4),
                  src + (size_t)r * ld + k0 + u * 8);
        }
    };

    const int nchunk = K / 64;                   // 32
    issue(0, 0); issue(1, 64);

    for (int c = 0; c < nchunk; c++) {
        cpa_wait<1>();
        __syncthreads();   // stage c ready; all warps done with stage c-1

        const bool more = (c + 2 < nchunk);
        const int  sn   = (c + 2) % 3;           // buffer last read at iter c-1
        const int  k0n  = (c + 2) * 64;

        const int s = c % 3;
        const uint32_t stA = sbase + s * GH_STAGE;
        const uint32_t stB = stA + GH_A;

#pragma unroll
        for (int ks = 0; ks < 4; ks++) {
            uint32_t af[4][4];
#pragma unroll
            for (int mi = 0; mi < 4; mi++) {
                int row = wm + 16 * mi + (lane & 15);
                int u   = 2 * ks + (lane >> 4);
                ldsm4(af[mi], stA + row * 128 + ((u ^ (row & 7)) << 4));
            }
#pragma unroll
            for (int nj = 0; nj < 4; nj++) {
                int row = wn + 16 * nj + (lane & 7) + ((lane & 16) >> 1);
                int u   = 2 * ks + ((lane >> 3) & 1);
                uint32_t t[4];
                ldsm4(t, stB + row * 128 + ((u ^ (row & 7)) << 4));
#pragma unroll
                for (int mi = 0; mi < 4; mi++) {
                    mma16(acc[mi][2 * nj],     af[mi], t);
                    mma16(acc[mi][2 * nj + 1], af[mi], t + 2);
                }
            }
            if (ks == 0 && more) issue_half(sn, k0n, 0);   // A half
            if (ks == 2 && more) issue_half(sn, k0n, 1);   // B half
        }
        cpa_commit();                            // exactly one group per chunk
    }

    const size_t rbase = (size_t)blockIdx.y * 128;
    const int cbase = blockIdx.x * GB_N;

    if (OUTF) {
        float* Cf = (float*)Cv;
#pragma unroll
        for (int mi = 0; mi < 4; mi++)
#pragma unroll
            for (int ni = 0; ni < 8; ni++) {
                size_t r = rbase + wm + mi * 16 + g;
                int    cc = cbase + wn + ni * 8 + tg * 2;
                float2 v0; v0.x = acc[mi][ni][0]; v0.y = acc[mi][ni][1];
                float2 v1; v1.x = acc[mi][ni][2]; v1.y = acc[mi][ni][3];
                *(float2*)(Cf + r * ldc + cc)       = v0;
                *(float2*)(Cf + (r + 8) * ldc + cc) = v1;
            }
        return;
    }

    __half* Ch = (__half*)Cv;
    if (!doRope) {
#pragma unroll
        for (int mi = 0; mi < 4; mi++)
#pragma unroll
            for (int ni = 0; ni < 8; ni++) {
                size_t r = rbase + wm + mi * 16 + g;
                int    cc = cbase + wn + ni * 8 + tg * 2;
                *(uint32_t*)(Ch + r * ldc + cc)       = packh2(acc[mi][ni][0], acc[mi][ni][1]);
                *(uint32_t*)(Ch + (r + 8) * ldc + cc) = packh2(acc[mi][ni][2], acc[mi][ni][3]);
            }
        return;
    }

    // ---- fused RoPE epilogue (this 128-wide N tile == exactly one head) ----
    __syncthreads();                 // protect ring reads before overwrite
    uint32_t* sT = (uint32_t*)dsm;   // 128 rows x 68 h2
#pragma unroll
    for (int mi = 0; mi < 4; mi++)
#pragma unroll
        for (int ni = 0; ni < 8; ni++) {
            int r  = wm + mi * 16 + g;
            int c2 = (wn + ni * 8 + tg * 2) >> 1;
            sT[r * RT_STRIDE + c2]       = packh2(acc[mi][ni][0], acc[mi][ni][1]);
            sT[(r + 8) * RT_STRIDE + c2] = packh2(acc[mi][ni][2], acc[mi][ni][3]);
        }
    __syncthreads();

    // 128 rows x 32 h2-dims = 4096 units, 32 per thread.
    // cos[d] == cos[d+64] (concat construction) -> one float2 per pair.
#pragma unroll
    for (int i = 0; i < 32; i++) {
        int idx  = tid + i * 128;
        int d2   = idx & 31;
        int row  = idx >> 5;
        int grow = (int)rbase + row;
        int pos  = grow & (Sc - 1);
        float2 cs = *(const float2*)(cb + pos * HDc + 2 * d2);
        float2 sn = *(const float2*)(sb + pos * HDc + 2 * d2);
        uint32_t u0 = sT[row * RT_STRIDE + d2];
        uint32_t u1 = sT[row * RT_STRIDE + d2 + 32];
        __half2 h0 = *(__half2*)&u0, h1 = *(__half2*)&u1;
        float x1a = __half2float(h0.x), x1b = __half2float(h0.y);
        float x2a = __half2float(h1.x), x2b = __half2float(h1.y);
        uint32_t o0 = packh2(x1a * cs.x - x2a * sn.x, x1b * cs.y - x2b * sn.y);
        uint32_t o1 = packh2(x2a * cs.x + x1a * sn.x, x2b * cs.y + x1b * sn.y);
        int gcol = cbase + 2 * d2;
        *(uint32_t*)(Ch + (size_t)grow * ldc + gcol)      = o0;
        *(uint32_t*)(Ch + (size_t)grow * ldc + gcol + 64) = o1;
    }
}

// Merged QKV projection with fused rope on Q,K: grid = (HS/128, MR/128, 3)
__global__ __launch_bounds__(128) void gemm_qkv(
    const __half* __restrict__ A,
    const __half* __restrict__ b0, const __half* __restrict__ b1,
    const __half* __restrict__ b2,
    __half* __restrict__ c0, __half* __restrict__ c1, __half* __restrict__ c2,
    const float* __restrict__ cb, const float* __restrict__ sb)
{
    extern __shared__ char dsm[];
    const __half* B = (blockIdx.z == 0) ? b0 : (blockIdx.z == 1) ? b1 : b2;
    __half*       C = (blockIdx.z == 0) ? c0 : (blockIdx.z == 1) ? c1 : c2;
    gemm_body<false>(A, B, C, HS, HS, HS, HS, dsm, cb, sb, blockIdx.z < 2);
}

// O projection (fp32 out): grid = (HS/128, MR/128)
__global__ __launch_bounds__(128) void gemm_o(
    const __half* __restrict__ A, const __half* __restrict__ B,
    float* __restrict__ C)
{
    extern __shared__ char dsm[];
    gemm_body<true>(A, B, C, HS, HS, HS, HS, dsm, nullptr, nullptr, false);
}

// ---------------------------------------------------------------------------
// FA2-style fused causal flash attention.
// 8 warps, warp w owns rows [16w, 16w+16). P in registers. K/V double-
// buffered; NEW: next-tile prefetch spread across the S-gemm ks-groups
// (K quarters at ks 0..3, V quarters at ks 4..7). One sync per k-tile.
// smem: Q 32K | K[2] 64K | V[2] 64K = 160 KB.
// ---------------------------------------------------------------------------
constexpr int F_Q    = 0;
constexpr int F_K0   = 32768;
constexpr int F_V0   = 98304;
constexpr int F_SMEM = 163840;

__global__ __launch_bounds__(256) void flash_h(
    const __half* __restrict__ Q, const __half* __restrict__ K,
    const __half* __restrict__ V, __half* __restrict__ O)
{
    extern __shared__ char dsm[];
    const uint32_t sbase = smem_u32(dsm);
    const uint32_t aQ = sbase + F_Q;

    const int qt = (int)gridDim.x - 1 - (int)blockIdx.x;
    const int bh = blockIdx.y;
    const int b = bh >> 4, h = bh & 15;
    const int tid  = threadIdx.x;
    const int lane = tid & 31, warp = tid >> 5;
    const int g = lane >> 2, tg = lane & 3;
    const int wr = warp * 16;

    const __half* Qb = Q + (size_t)(b * Sc + qt * 128) * HS + h * HDc;
    const __half* Kb = K + (size_t)(b * Sc) * HS + h * HDc;
    const __half* Vb = V + (size_t)(b * Sc) * HS + h * HDc;

    auto load_tile = [&](uint32_t adst, const __half* src, int ktile) {
        const __half* p = src + (size_t)(ktile * 128) * HS;
#pragma unroll
        for (int i = 0; i < 8; i++) {
            int idx = tid + i * 256;
            int r = idx >> 4, u = idx & 15;
            cpa16(adst + r * 256 + ((u ^ (r & 7)) << 4), p + (size_t)r * HS + u * 8);
        }
    };
    // Quarter of a tile: iterations [i0, i0+2)
    auto load_part = [&](uint32_t adst, const __half* src, int ktile, int i0) {
        const __half* p = src + (size_t)(ktile * 128) * HS;
#pragma unroll
        for (int i = 0; i < 2; i++) {
            int idx = tid + (i0 + i) * 256;
            int r = idx >> 4, u = idx & 15;
            cpa16(adst + r * 256 + ((u ^ (r & 7)) << 4), p + (size_t)r * HS + u * 8);
        }
    };

#pragma unroll
    for (int i = 0; i < 8; i++) {
        int idx = tid + i * 256;
        int r = idx >> 4, u = idx & 15;
        cpa16(aQ + r * 256 + ((u ^ (r & 7)) << 4), Qb + (size_t)r * HS + u * 8);
    }
    load_tile(sbase + F_K0, Kb, 0);
    load_tile(sbase + F_V0, Vb, 0);
    cpa_commit();

    float acc_o[16][4];
#pragma unroll
    for (int ni = 0; ni < 16; ni++)
#pragma unroll
        for (int j = 0; j < 4; j++) acc_o[ni][j] = 0.f;
    float m0 = -1e30f, m1 = -1e30f, l0 = 0.f, l1 = 0.f;

    for (int kt = 0; kt <= qt; kt++) {
        cpa_wait<0>();
        __syncthreads();          // K[kt]/V[kt] visible; all warps done with kt-1

        const bool pref = (kt < qt);
        const int  nb   = (kt + 1) & 1;
        const uint32_t nK = sbase + F_K0 + nb * 32768;
        const uint32_t nV = sbase + F_V0 + nb * 32768;
        const uint32_t cK = sbase + F_K0 + (kt & 1) * 32768;
        const uint32_t cV = sbase + F_V0 + (kt & 1) * 32768;

        float accs[16][4];
#pragma unroll
        for (int ni = 0; ni < 16; ni++)
#pragma unroll
            for (int j = 0; j < 4; j++) accs[ni][j] = 0.f;

#pragma unroll
        for (int ks = 0; ks < 8; ks++) {
            uint32_t a[4];
            {
                int row = wr + (lane & 15);
                int u   = 2 * ks + (lane >> 4);
                ldsm4(a, aQ + row * 256 + ((u ^ (row & 7)) << 4));
            }
#pragma unroll
            for (int nj = 0; nj < 8; nj++) {
                int row = 16 * nj + (lane & 7) + ((lane & 16) >> 1);
                int u   = 2 * ks + ((lane >> 3) & 1);
                uint32_t t[4];
                ldsm4(t, cK + row * 256 + ((u ^ (row & 7)) << 4));
                mma16(accs[2 * nj],     a, t);
                mma16(accs[2 * nj + 1], a, t + 2);
            }
            if (pref) {
                if (ks < 4) load_part(nK, Kb, kt + 1, ks * 2);
                else        load_part(nV, Vb, kt + 1, (ks - 4) * 2);
                if (ks == 3 || ks == 7) cpa_commit();
            }
        }

        const bool diag = (kt == qt);
        const int r0 = wr + g, r1 = r0 + 8;
#pragma unroll
        for (int ni = 0; ni < 16; ni++) {
            int c0 = ni * 8 + tg * 2, c1 = c0 + 1;
            accs[ni][0] *= SCALE; accs[ni][1] *= SCALE;
            accs[ni][2] *= SCALE; accs[ni][3] *= SCALE;
            if (diag) {
                if (c0 > r0) accs[ni][0] = -1e30f;
                if (c1 > r0) accs[ni][1] = -1e30f;
                if (c0 > r1) accs[ni][2] = -1e30f;
                if (c1 > r1) accs[ni][3] = -1e30f;
            }
        }

        float lm0 = -1e30f, lm1 = -1e30f;
#pragma unroll
        for (int ni = 0; ni < 16; ni++) {
            lm0 = fmaxf(lm0, fmaxf(accs[ni][0], accs[ni][1]));
            lm1 = fmaxf(lm1, fmaxf(accs[ni][2], accs[ni][3]));
        }
        lm0 = fmaxf(lm0, __shfl_xor_sync(0xffffffffu, lm0, 1));
        lm0 = fmaxf(lm0, __shfl_xor_sync(0xffffffffu, lm0, 2));
        lm1 = fmaxf(lm1, __shfl_xor_sync(0xffffffffu, lm1, 1));
        lm1 = fmaxf(lm1, __shfl_xor_sync(0xffffffffu, lm1, 2));

        float mn0 = fmaxf(m0, lm0), mn1 = fmaxf(m1, lm1);
        float cr0 = __expf(m0 - mn0), cr1 = __expf(m1 - mn1);
        m0 = mn0; m1 = mn1;

        uint32_t ph[16][2];
        float ls0 = 0.f, ls1 = 0.f;
#pragma unroll
        for (int ni = 0; ni < 16; ni++) {
            float p0 = __expf(accs[ni][0] - mn0);
            float p1 = __expf(accs[ni][1] - mn0);
            float p2 = __expf(accs[ni][2] - mn1);
            float p3 = __expf(accs[ni][3] - mn1);
            ls0 += p0 + p1; ls1 += p2 + p3;
            ph[ni][0] = packh2(p0, p1);
            ph[ni][1] = packh2(p2, p3);
            acc_o[ni][0] *= cr0; acc_o[ni][1] *= cr0;
            acc_o[ni][2] *= cr1; acc_o[ni][3] *= cr1;
        }
        ls0 += __shfl_xor_sync(0xffffffffu, ls0, 1);
        ls0 += __shfl_xor_sync(0xffffffffu, ls0, 2);
        ls1 += __shfl_xor_sync(0xffffffffu, ls1, 1);
        ls1 += __shfl_xor_sync(0xffffffffu, ls1, 2);
        l0 = l0 * cr0 + ls0;
        l1 = l1 * cr1 + ls1;

#pragma unroll
        for (int ks = 0; ks < 8; ks++) {
            uint32_t a[4] = { ph[2 * ks][0], ph[2 * ks][1],
                              ph[2 * ks + 1][0], ph[2 * ks + 1][1] };
#pragma unroll
            for (int nj = 0; nj < 8; nj++) {
                int rowv = 16 * ks + (lane & 7) + (lane & 8);
                int u    = 2 * nj + (lane >> 4);
                uint32_t t[4];
                ldsm4t(t, cV + rowv * 256 + ((u ^ (rowv & 7)) << 4));
                mma16(acc_o[2 * nj],     a, t);
                mma16(acc_o[2 * nj + 1], a, t + 2);
            }
        }
    }

    __half* Ob = O + (size_t)(b * Sc + qt * 128) * HS + h * HDc;
    const float inv0 = 1.f / l0, inv1 = 1.f / l1;
    const int r0 = wr + g, r1 = r0 + 8;
#pragma unroll
    for (int ni = 0; ni < 16; ni++) {
        int c = ni * 8 + tg * 2;
        *(uint32_t*)(Ob + (size_t)r0 * HS + c) =
            packh2(acc_o[ni][0] * inv0, acc_o[ni][1] * inv0);
        *(uint32_t*)(Ob + (size_t)r1 * HS + c) =
            packh2(acc_o[ni][2] * inv1, acc_o[ni][3] * inv1);
    }
}

// ---------------------------------------------------------------------------
// Launcher
// ---------------------------------------------------------------------------
extern "C" void kernel_launch(void* const* d_in, const int* in_sizes, int n_in,
                              void* d_out, int out_size)
{
    const float* hs = (const float*)d_in[0];
    const float* wq = (const float*)d_in[1];
    const float* wk = (const float*)d_in[2];
    const float* wv = (const float*)d_in[3];
    const float* wo = (const float*)d_in[4];
    const float* cb = (const float*)d_in[5];
    const float* sb = (const float*)d_in[6];
    float* out = (float*)d_out;

    __half *qp, *kp, *vp, *aop, *hsp, *wqp, *wkp, *wvp, *wop;
    cudaGetSymbolAddress((void**)&qp,  g_q);
    cudaGetSymbolAddress((void**)&kp,  g_k);
    cudaGetSymbolAddress((void**)&vp,  g_v);
    cudaGetSymbolAddress((void**)&aop, g_ao);
    cudaGetSymbolAddress((void**)&hsp, g_hs);
    cudaGetSymbolAddress((void**)&wqp, g_wq);
    cudaGetSymbolAddress((void**)&wkp, g_wk);
    cudaGetSymbolAddress((void**)&wvp, g_wv);
    cudaGetSymbolAddress((void**)&wop, g_wo);

    cudaFuncSetAttribute(gemm_qkv, cudaFuncAttributeMaxDynamicSharedMemorySize, GH_SMEM);
    cudaFuncSetAttribute(gemm_o,   cudaFuncAttributeMaxDynamicSharedMemorySize, GH_SMEM);
    cudaFuncSetAttribute(flash_h,  cudaFuncAttributeMaxDynamicSharedMemorySize, F_SMEM);

    round_all<<<dim3(MR * HS / 4 / 1024, 5), 256>>>(
        (const float4*)hs, (const float4*)wq, (const float4*)wk,
        (const float4*)wv, (const float4*)wo,
        (uint2*)hsp, (uint2*)wqp, (uint2*)wkp, (uint2*)wvp, (uint2*)wop);

    gemm_qkv<<<dim3(HS / GB_N, MR / 128, 3), 128, GH_SMEM>>>(
        hsp, wqp, wkp, wvp, qp, kp, vp, cb, sb);

    flash_h<<<dim3(Sc / 128, BHc), 256, F_SMEM>>>(qp, kp, vp, aop);

    gemm_o<<<dim3(HS / GB_N, MR / 128), 128, GH_SMEM>>>(aop, wop, out);
}

// round 14
// speedup vs baseline: 1.0184x; 1.0184x over previous
#include <cuda_runtime.h>
#include <cuda_fp16.h>
#include <cstdint>
#include <cstddef>

// Problem constants
constexpr int Bc  = 2;
constexpr int Sc  = 2048;
constexpr int HS  = 2048;
constexpr int NHc = 16;
constexpr int HDc = 128;
constexpr int MR  = Bc * Sc;    // 4096 rows of (b, s)
constexpr int BHc = Bc * NHc;   // 32 (batch*heads)
constexpr float SCALE = 0.08838834764831845f;  // 1/sqrt(128)

// Scratch (device globals — allocation-free per harness rules)
__device__ __half g_q [MR * HS];
__device__ __half g_k [MR * HS];
__device__ __half g_v [MR * HS];
__device__ __half g_ao[MR * HS];
__device__ __half g_hs[MR * HS];
__device__ __half g_wq[HS * HS];
__device__ __half g_wk[HS * HS];
__device__ __half g_wv[HS * HS];
__device__ __half g_wo[HS * HS];

// ---------------------------------------------------------------------------
// Helpers
// ---------------------------------------------------------------------------
__device__ __forceinline__ uint32_t smem_u32(const void* p) {
    uint32_t a;
    asm("{ .reg .u64 t; cvta.to.shared.u64 t, %1; cvt.u32.u64 %0, t; }"
        : "=r"(a) : "l"(p));
    return a;
}
__device__ __forceinline__ void cpa16(uint32_t dst, const void* src) {
    asm volatile("cp.async.cg.shared.global [%0], [%1], 16;"
                 :: "r"(dst), "l"(src) : "memory");
}
__device__ __forceinline__ void cpa_commit() {
    asm volatile("cp.async.commit_group;" ::: "memory");
}
template <int N>
__device__ __forceinline__ void cpa_wait() {
    asm volatile("cp.async.wait_group %0;" :: "n"(N) : "memory");
}
__device__ __forceinline__ void ldsm4(uint32_t* r, uint32_t a) {
    asm volatile("ldmatrix.sync.aligned.m8n8.x4.shared.b16 {%0,%1,%2,%3}, [%4];"
                 : "=r"(r[0]), "=r"(r[1]), "=r"(r[2]), "=r"(r[3]) : "r"(a));
}
__device__ __forceinline__ void ldsm4t(uint32_t* r, uint32_t a) {
    asm volatile("ldmatrix.sync.aligned.m8n8.x4.trans.shared.b16 {%0,%1,%2,%3}, [%4];"
                 : "=r"(r[0]), "=r"(r[1]), "=r"(r[2]), "=r"(r[3]) : "r"(a));
}
__device__ __forceinline__ void mma16(float* c, const uint32_t* a, const uint32_t* b) {
    asm volatile(
        "mma.sync.aligned.m16n8k16.row.col.f32.f16.f16.f32 "
        "{%0,%1,%2,%3},{%4,%5,%6,%7},{%8,%9},{%0,%1,%2,%3};\n"
        : "+f"(c[0]), "+f"(c[1]), "+f"(c[2]), "+f"(c[3])
        : "r"(a[0]), "r"(a[1]), "r"(a[2]), "r"(a[3]),
          "r"(b[0]), "r"(b[1]));
}
__device__ __forceinline__ uint32_t packh2(float a, float b) {
    __half2 h = __floats2half2_rn(a, b);
    return *(uint32_t*)&h;
}

// ---------------------------------------------------------------------------
// Merged fp16 conversion, 4 float4 per thread (MLP=4).
// grid = (2048, 5). y=0: hs (n4=2M uses all blocks); y=1..4: weights (n4=1M).
// ---------------------------------------------------------------------------
__global__ __launch_bounds__(256) void round_all(
    const float4* __restrict__ hs, const float4* __restrict__ w0,
    const float4* __restrict__ w1, const float4* __restrict__ w2,
    const float4* __restrict__ w3,
    uint2* __restrict__ ohs, uint2* __restrict__ o0, uint2* __restrict__ o1,
    uint2* __restrict__ o2, uint2* __restrict__ o3)
{
    const int y = blockIdx.y;
    const float4* in  = (y == 0) ? hs : (y == 1) ? w0 : (y == 2) ? w1
                      : (y == 3) ? w2 : w3;
    uint2*        out = (y == 0) ? ohs : (y == 1) ? o0 : (y == 2) ? o1
                      : (y == 3) ? o2 : o3;
    const int n4 = (y == 0) ? (MR * HS / 4) : (HS * HS / 4);
    const int base = blockIdx.x * 1024 + threadIdx.x;
    if (base >= n4) return;

    float4 v[4];
    int   idx[4];
    int   cnt = 0;
#pragma unroll
    for (int i = 0; i < 4; i++) {
        int j = base + i * 256;
        if (j < n4) { idx[cnt] = j; v[cnt] = in[j]; cnt++; }
    }
#pragma unroll
    for (int i = 0; i < 4; i++) {
        if (i < cnt) {
            uint2 o;
            o.x = packh2(v[i].x, v[i].y);
            o.y = packh2(v[i].z, v[i].w);
            out[idx[i]] = o;
        }
    }
}

// ---------------------------------------------------------------------------
// fp16 TN GEMM: C[M,N] = A[M,K] * B[N,K]^T      (round-12 configuration)
// Block tile 128x128, 4 warps (2x2) of 64x64, BK=64 halves, 128 threads.
// 3-stage cp.async ring (32KB/stage = 96KB) -> 2 CTAs/SM.
// Optional fused RoPE epilogue (doRope).
// ---------------------------------------------------------------------------
constexpr int GB_N      = 128;
constexpr int GH_A      = 128 * 128;          // bytes per operand per stage
constexpr int GH_STAGE  = 2 * GH_A;           // 32768
constexpr int GH_SMEM   = 3 * GH_STAGE;       // 98304
constexpr int RT_STRIDE = 68;                 // h2 per staged row (64 + pad)

template <bool OUTF>
__device__ __forceinline__ void gemm_body(
    const __half* __restrict__ A, const __half* __restrict__ B,
    void* __restrict__ Cv, int lda, int ldb, int ldc, int K, char* dsm,
    const float* __restrict__ cb, const float* __restrict__ sb, bool doRope)
{
    const uint32_t sbase = smem_u32(dsm);
    const int tid  = threadIdx.x;               // 0..127
    const int lane = tid & 31, warp = tid >> 5; // warp 0..3
    const int g = lane >> 2, tg = lane & 3;
    const int wm = (warp >> 1) * 64;            // 0 or 64
    const int wn = (warp & 1) * 64;             // 0 or 64

    const __half* Ab = A + (size_t)blockIdx.y * 128 * lda;
    const __half* Bb = B + (size_t)blockIdx.x * GB_N * ldb;

    float acc[4][8][4];
#pragma unroll
    for (int mi = 0; mi < 4; mi++)
#pragma unroll
        for (int ni = 0; ni < 8; ni++)
#pragma unroll
            for (int j = 0; j < 4; j++) acc[mi][ni][j] = 0.f;

    auto issue = [&](int s, int k0) {
        const uint32_t stA = sbase + s * GH_STAGE;
        const uint32_t stB = stA + GH_A;
#pragma unroll
        for (int i = 0; i < 8; i++) {            // A: 1024 16B units
            int idx = tid + i * 128;
            int r = idx >> 3, u = idx & 7;
            cpa16(stA + r * 128 + ((u ^ (r & 7)) << 4),
                  Ab + (size_t)r * lda + k0 + u * 8);
        }
#pragma unroll
        for (int i = 0; i < 8; i++) {            // B: 1024 16B units
            int idx = tid + i * 128;
            int r = idx >> 3, u = idx & 7;
            cpa16(stB + r * 128 + ((u ^ (r & 7)) << 4),
                  Bb + (size_t)r * ldb + k0 + u * 8);
        }
        cpa_commit();
    };

    const int nchunk = K / 64;                   // 32
    issue(0, 0); issue(1, 64);

    for (int c = 0; c < nchunk; c++) {
        cpa_wait<1>();
        __syncthreads();   // stage c ready; all warps done with stage c-1

        if (c + 2 < nchunk) issue((c + 2) % 3, (c + 2) * 64);
        else                cpa_commit();        // uniform group count

        const int s = c % 3;
        const uint32_t stA = sbase + s * GH_STAGE;
        const uint32_t stB = stA + GH_A;

#pragma unroll
        for (int ks = 0; ks < 4; ks++) {
            uint32_t af[4][4];
#pragma unroll
            for (int mi = 0; mi < 4; mi++) {
                int row = wm + 16 * mi + (lane & 15);
                int u   = 2 * ks + (lane >> 4);
                ldsm4(af[mi], stA + row * 128 + ((u ^ (row & 7)) << 4));
            }
#pragma unroll
            for (int nj = 0; nj < 4; nj++) {
                int row = wn + 16 * nj + (lane & 7) + ((lane & 16) >> 1);
                int u   = 2 * ks + ((lane >> 3) & 1);
                uint32_t t[4];
                ldsm4(t, stB + row * 128 + ((u ^ (row & 7)) << 4));
#pragma unroll
                for (int mi = 0; mi < 4; mi++) {
                    mma16(acc[mi][2 * nj],     af[mi], t);
                    mma16(acc[mi][2 * nj + 1], af[mi], t + 2);
                }
            }
        }
    }

    const size_t rbase = (size_t)blockIdx.y * 128;
    const int cbase = blockIdx.x * GB_N;

    if (OUTF) {
        float* Cf = (float*)Cv;
#pragma unroll
        for (int mi = 0; mi < 4; mi++)
#pragma unroll
            for (int ni = 0; ni < 8; ni++) {
                size_t r = rbase + wm + mi * 16 + g;
                int    cc = cbase + wn + ni * 8 + tg * 2;
                float2 v0; v0.x = acc[mi][ni][0]; v0.y = acc[mi][ni][1];
                float2 v1; v1.x = acc[mi][ni][2]; v1.y = acc[mi][ni][3];
                *(float2*)(Cf + r * ldc + cc)       = v0;
                *(float2*)(Cf + (r + 8) * ldc + cc) = v1;
            }
        return;
    }

    __half* Ch = (__half*)Cv;
    if (!doRope) {
#pragma unroll
        for (int mi = 0; mi < 4; mi++)
#pragma unroll
            for (int ni = 0; ni < 8; ni++) {
                size_t r = rbase + wm + mi * 16 + g;
                int    cc = cbase + wn + ni * 8 + tg * 2;
                *(uint32_t*)(Ch + r * ldc + cc)       = packh2(acc[mi][ni][0], acc[mi][ni][1]);
                *(uint32_t*)(Ch + (r + 8) * ldc + cc) = packh2(acc[mi][ni][2], acc[mi][ni][3]);
            }
        return;
    }

    // ---- fused RoPE epilogue (this 128-wide N tile == exactly one head) ----
    __syncthreads();                 // protect ring reads before overwrite
    uint32_t* sT = (uint32_t*)dsm;   // 128 rows x 68 h2
#pragma unroll
    for (int mi = 0; mi < 4; mi++)
#pragma unroll
        for (int ni = 0; ni < 8; ni++) {
            int r  = wm + mi * 16 + g;
            int c2 = (wn + ni * 8 + tg * 2) >> 1;
            sT[r * RT_STRIDE + c2]       = packh2(acc[mi][ni][0], acc[mi][ni][1]);
            sT[(r + 8) * RT_STRIDE + c2] = packh2(acc[mi][ni][2], acc[mi][ni][3]);
        }
    __syncthreads();

    // 128 rows x 32 h2-dims = 4096 units, 32 per thread.
    // cos[d] == cos[d+64] (concat construction) -> one float2 per pair.
#pragma unroll
    for (int i = 0; i < 32; i++) {
        int idx  = tid + i * 128;
        int d2   = idx & 31;
        int row  = idx >> 5;
        int grow = (int)rbase + row;
        int pos  = grow & (Sc - 1);
        float2 cs = *(const float2*)(cb + pos * HDc + 2 * d2);
        float2 sn = *(const float2*)(sb + pos * HDc + 2 * d2);
        uint32_t u0 = sT[row * RT_STRIDE + d2];
        uint32_t u1 = sT[row * RT_STRIDE + d2 + 32];
        __half2 h0 = *(__half2*)&u0, h1 = *(__half2*)&u1;
        float x1a = __half2float(h0.x), x1b = __half2float(h0.y);
        float x2a = __half2float(h1.x), x2b = __half2float(h1.y);
        uint32_t o0 = packh2(x1a * cs.x - x2a * sn.x, x1b * cs.y - x2b * sn.y);
        uint32_t o1 = packh2(x2a * cs.x + x1a * sn.x, x2b * cs.y + x1b * sn.y);
        int gcol = cbase + 2 * d2;
        *(uint32_t*)(Ch + (size_t)grow * ldc + gcol)      = o0;
        *(uint32_t*)(Ch + (size_t)grow * ldc + gcol + 64) = o1;
    }
}

// Merged QKV projection with fused rope on Q,K: grid = (HS/128, MR/128, 3)
__global__ __launch_bounds__(128) void gemm_qkv(
    const __half* __restrict__ A,
    const __half* __restrict__ b0, const __half* __restrict__ b1,
    const __half* __restrict__ b2,
    __half* __restrict__ c0, __half* __restrict__ c1, __half* __restrict__ c2,
    const float* __restrict__ cb, const float* __restrict__ sb)
{
    extern __shared__ char dsm[];
    const __half* B = (blockIdx.z == 0) ? b0 : (blockIdx.z == 1) ? b1 : b2;
    __half*       C = (blockIdx.z == 0) ? c0 : (blockIdx.z == 1) ? c1 : c2;
    gemm_body<false>(A, B, C, HS, HS, HS, HS, dsm, cb, sb, blockIdx.z < 2);
}

// O projection (fp32 out): grid = (HS/128, MR/128)
__global__ __launch_bounds__(128) void gemm_o(
    const __half* __restrict__ A, const __half* __restrict__ B,
    float* __restrict__ C)
{
    extern __shared__ char dsm[];
    gemm_body<true>(A, B, C, HS, HS, HS, HS, dsm, nullptr, nullptr, false);
}

// ---------------------------------------------------------------------------
// FA2-style fused causal flash attention (round-12 structure).
// 8 warps, warp w owns rows [16w, 16w+16). P in registers. K/V double-
// buffered with cross-iteration prefetch; one __syncthreads per k-tile.
// NEW vs round 12: Q fragments hoisted into registers once (qf[8][4]) —
// removes the per-iteration Q ldsm4 and all sQ re-reads. Values identical.
// smem: Q 32K | K[2] 64K | V[2] 64K = 160 KB.
// ---------------------------------------------------------------------------
constexpr int F_Q    = 0;
constexpr int F_K0   = 32768;
constexpr int F_V0   = 98304;
constexpr int F_SMEM = 163840;

__global__ __launch_bounds__(256) void flash_h(
    const __half* __restrict__ Q, const __half* __restrict__ K,
    const __half* __restrict__ V, __half* __restrict__ O)
{
    extern __shared__ char dsm[];
    const uint32_t sbase = smem_u32(dsm);
    const uint32_t aQ = sbase + F_Q;

    const int qt = (int)gridDim.x - 1 - (int)blockIdx.x;
    const int bh = blockIdx.y;
    const int b = bh >> 4, h = bh & 15;
    const int tid  = threadIdx.x;
    const int lane = tid & 31, warp = tid >> 5;
    const int g = lane >> 2, tg = lane & 3;
    const int wr = warp * 16;

    const __half* Qb = Q + (size_t)(b * Sc + qt * 128) * HS + h * HDc;
    const __half* Kb = K + (size_t)(b * Sc) * HS + h * HDc;
    const __half* Vb = V + (size_t)(b * Sc) * HS + h * HDc;

    auto load_tile = [&](uint32_t adst, const __half* src, int ktile) {
        const __half* p = src + (size_t)(ktile * 128) * HS;
#pragma unroll
        for (int i = 0; i < 8; i++) {
            int idx = tid + i * 256;
            int r = idx >> 4, u = idx & 15;
            cpa16(adst + r * 256 + ((u ^ (r & 7)) << 4), p + (size_t)r * HS + u * 8);
        }
    };

#pragma unroll
    for (int i = 0; i < 8; i++) {
        int idx = tid + i * 256;
        int r = idx >> 4, u = idx & 15;
        cpa16(aQ + r * 256 + ((u ^ (r & 7)) << 4), Qb + (size_t)r * HS + u * 8);
    }
    load_tile(sbase + F_K0, Kb, 0);
    load_tile(sbase + F_V0, Vb, 0);
    cpa_commit();

    // Hoist Q fragments into registers (bit-identical to per-iter ldsm).
    cpa_wait<0>();
    __syncthreads();
    uint32_t qf[8][4];
#pragma unroll
    for (int ks = 0; ks < 8; ks++) {
        int row = wr + (lane & 15);
        int u   = 2 * ks + (lane >> 4);
        ldsm4(qf[ks], aQ + row * 256 + ((u ^ (row & 7)) << 4));
    }

    float acc_o[16][4];
#pragma unroll
    for (int ni = 0; ni < 16; ni++)
#pragma unroll
        for (int j = 0; j < 4; j++) acc_o[ni][j] = 0.f;
    float m0 = -1e30f, m1 = -1e30f, l0 = 0.f, l1 = 0.f;

    for (int kt = 0; kt <= qt; kt++) {
        cpa_wait<0>();            // no-op at kt=0 (all groups drained above)
        __syncthreads();          // K[kt]/V[kt] visible; warps done with kt-1

        if (kt < qt) {
            const int nb = (kt + 1) & 1;
            load_tile(sbase + F_K0 + nb * 32768, Kb, kt + 1);
            cpa_commit();
            load_tile(sbase + F_V0 + nb * 32768, Vb, kt + 1);
            cpa_commit();
        }
        const uint32_t cK = sbase + F_K0 + (kt & 1) * 32768;
        const uint32_t cV = sbase + F_V0 + (kt & 1) * 32768;

        float accs[16][4];
#pragma unroll
        for (int ni = 0; ni < 16; ni++)
#pragma unroll
            for (int j = 0; j < 4; j++) accs[ni][j] = 0.f;

#pragma unroll
        for (int ks = 0; ks < 8; ks++) {
#pragma unroll
            for (int nj = 0; nj < 8; nj++) {
                int row = 16 * nj + (lane & 7) + ((lane & 16) >> 1);
                int u   = 2 * ks + ((lane >> 3) & 1);
                uint32_t t[4];
                ldsm4(t, cK + row * 256 + ((u ^ (row & 7)) << 4));
                mma16(accs[2 * nj],     qf[ks], t);
                mma16(accs[2 * nj + 1], qf[ks], t + 2);
            }
        }

        const bool diag = (kt == qt);
        const int r0 = wr + g, r1 = r0 + 8;
#pragma unroll
        for (int ni = 0; ni < 16; ni++) {
            int c0 = ni * 8 + tg * 2, c1 = c0 + 1;
            accs[ni][0] *= SCALE; accs[ni][1] *= SCALE;
            accs[ni][2] *= SCALE; accs[ni][3] *= SCALE;
            if (diag) {
                if (c0 > r0) accs[ni][0] = -1e30f;
                if (c1 > r0) accs[ni][1] = -1e30f;
                if (c0 > r1) accs[ni][2] = -1e30f;
                if (c1 > r1) accs[ni][3] = -1e30f;
            }
        }

        float lm0 = -1e30f, lm1 = -1e30f;
#pragma unroll
        for (int ni = 0; ni < 16; ni++) {
            lm0 = fmaxf(lm0, fmaxf(accs[ni][0], accs[ni][1]));
            lm1 = fmaxf(lm1, fmaxf(accs[ni][2], accs[ni][3]));
        }
        lm0 = fmaxf(lm0, __shfl_xor_sync(0xffffffffu, lm0, 1));
        lm0 = fmaxf(lm0, __shfl_xor_sync(0xffffffffu, lm0, 2));
        lm1 = fmaxf(lm1, __shfl_xor_sync(0xffffffffu, lm1, 1));
        lm1 = fmaxf(lm1, __shfl_xor_sync(0xffffffffu, lm1, 2));

        float mn0 = fmaxf(m0, lm0), mn1 = fmaxf(m1, lm1);
        float cr0 = __expf(m0 - mn0), cr1 = __expf(m1 - mn1);
        m0 = mn0; m1 = mn1;

        uint32_t ph[16][2];
        float ls0 = 0.f, ls1 = 0.f;
#pragma unroll
        for (int ni = 0; ni < 16; ni++) {
            float p0 = __expf(accs[ni][0] - mn0);
            float p1 = __expf(accs[ni][1] - mn0);
            float p2 = __expf(accs[ni][2] - mn1);
            float p3 = __expf(accs[ni][3] - mn1);
            ls0 += p0 + p1; ls1 += p2 + p3;
            ph[ni][0] = packh2(p0, p1);
            ph[ni][1] = packh2(p2, p3);
            acc_o[ni][0] *= cr0; acc_o[ni][1] *= cr0;
            acc_o[ni][2] *= cr1; acc_o[ni][3] *= cr1;
        }
        ls0 += __shfl_xor_sync(0xffffffffu, ls0, 1);
        ls0 += __shfl_xor_sync(0xffffffffu, ls0, 2);
        ls1 += __shfl_xor_sync(0xffffffffu, ls1, 1);
        ls1 += __shfl_xor_sync(0xffffffffu, ls1, 2);
        l0 = l0 * cr0 + ls0;
        l1 = l1 * cr1 + ls1;

#pragma unroll
        for (int ks = 0; ks < 8; ks++) {
            uint32_t a[4] = { ph[2 * ks][0], ph[2 * ks][1],
                              ph[2 * ks + 1][0], ph[2 * ks + 1][1] };
#pragma unroll
            for (int nj = 0; nj < 8; nj++) {
                int rowv = 16 * ks + (lane & 7) + (lane & 8);
                int u    = 2 * nj + (lane >> 4);
                uint32_t t[4];
                ldsm4t(t, cV + rowv * 256 + ((u ^ (rowv & 7)) << 4));
                mma16(acc_o[2 * nj],     a, t);
                mma16(acc_o[2 * nj + 1], a, t + 2);
            }
        }
    }

    __half* Ob = O + (size_t)(b * Sc + qt * 128) * HS + h * HDc;
    const float inv0 = 1.f / l0, inv1 = 1.f / l1;
    const int r0 = wr + g, r1 = r0 + 8;
#pragma unroll
    for (int ni = 0; ni < 16; ni++) {
        int c = ni * 8 + tg * 2;
        *(uint32_t*)(Ob + (size_t)r0 * HS + c) =
            packh2(acc_o[ni][0] * inv0, acc_o[ni][1] * inv0);
        *(uint32_t*)(Ob + (size_t)r1 * HS + c) =
            packh2(acc_o[ni][2] * inv1, acc_o[ni][3] * inv1);
    }
}

// ---------------------------------------------------------------------------
// Launcher
// ---------------------------------------------------------------------------
extern "C" void kernel_launch(void* const* d_in, const int* in_sizes, int n_in,
                              void* d_out, int out_size)
{
    const float* hs = (const float*)d_in[0];
    const float* wq = (const float*)d_in[1];
    const float* wk = (const float*)d_in[2];
    const float* wv = (const float*)d_in[3];
    const float* wo = (const float*)d_in[4];
    const float* cb = (const float*)d_in[5];
    const float* sb = (const float*)d_in[6];
    float* out = (float*)d_out;

    __half *qp, *kp, *vp, *aop, *hsp, *wqp, *wkp, *wvp, *wop;
    cudaGetSymbolAddress((void**)&qp,  g_q);
    cudaGetSymbolAddress((void**)&kp,  g_k);
    cudaGetSymbolAddress((void**)&vp,  g_v);
    cudaGetSymbolAddress((void**)&aop, g_ao);
    cudaGetSymbolAddress((void**)&hsp, g_hs);
    cudaGetSymbolAddress((void**)&wqp, g_wq);
    cudaGetSymbolAddress((void**)&wkp, g_wk);
    cudaGetSymbolAddress((void**)&wvp, g_wv);
    cudaGetSymbolAddress((void**)&wop, g_wo);

    cudaFuncSetAttribute(gemm_qkv, cudaFuncAttributeMaxDynamicSharedMemorySize, GH_SMEM);
    cudaFuncSetAttribute(gemm_o,   cudaFuncAttributeMaxDynamicSharedMemorySize, GH_SMEM);
    cudaFuncSetAttribute(flash_h,  cudaFuncAttributeMaxDynamicSharedMemorySize, F_SMEM);

    round_all<<<dim3(MR * HS / 4 / 1024, 5), 256>>>(
        (const float4*)hs, (const float4*)wq, (const float4*)wk,
        (const float4*)wv, (const float4*)wo,
        (uint2*)hsp, (uint2*)wqp, (uint2*)wkp, (uint2*)wvp, (uint2*)wop);

    gemm_qkv<<<dim3(HS / GB_N, MR / 128, 3), 128, GH_SMEM>>>(
        hsp, wqp, wkp, wvp, qp, kp, vp, cb, sb);

    flash_h<<<dim3(Sc / 128, BHc), 256, F_SMEM>>>(qp, kp, vp, aop);

    gemm_o<<<dim3(HS / GB_N, MR / 128), 128, GH_SMEM>>>(aop, wop, out);
}

// round 15
// speedup vs baseline: 1.0322x; 1.0136x over previous
#include <cuda_runtime.h>
#include <cuda_fp16.h>
#include <cstdint>
#include <cstddef>

// Problem constants
constexpr int Bc  = 2;
constexpr int Sc  = 2048;
constexpr int HS  = 2048;
constexpr int NHc = 16;
constexpr int HDc = 128;
constexpr int MR  = Bc * Sc;    // 4096 rows of (b, s)
constexpr int BHc = Bc * NHc;   // 32 (batch*heads)
constexpr float SCALE = 0.08838834764831845f;  // 1/sqrt(128)

// Scratch (device globals — allocation-free per harness rules)
__device__ __half g_q [MR * HS];
__device__ __half g_k [MR * HS];
__device__ __half g_v [MR * HS];
__device__ __half g_ao[MR * HS];
__device__ __half g_hs[MR * HS];
__device__ __half g_wq[HS * HS];
__device__ __half g_wk[HS * HS];
__device__ __half g_wv[HS * HS];
__device__ __half g_wo[HS * HS];

// ---------------------------------------------------------------------------
// Helpers
// ---------------------------------------------------------------------------
__device__ __forceinline__ uint32_t smem_u32(const void* p) {
    uint32_t a;
    asm("{ .reg .u64 t; cvta.to.shared.u64 t, %1; cvt.u32.u64 %0, t; }"
        : "=r"(a) : "l"(p));
    return a;
}
__device__ __forceinline__ void cpa16(uint32_t dst, const void* src) {
    asm volatile("cp.async.cg.shared.global [%0], [%1], 16;"
                 :: "r"(dst), "l"(src) : "memory");
}
__device__ __forceinline__ void cpa_commit() {
    asm volatile("cp.async.commit_group;" ::: "memory");
}
template <int N>
__device__ __forceinline__ void cpa_wait() {
    asm volatile("cp.async.wait_group %0;" :: "n"(N) : "memory");
}
__device__ __forceinline__ void ldsm4(uint32_t* r, uint32_t a) {
    asm volatile("ldmatrix.sync.aligned.m8n8.x4.shared.b16 {%0,%1,%2,%3}, [%4];"
                 : "=r"(r[0]), "=r"(r[1]), "=r"(r[2]), "=r"(r[3]) : "r"(a));
}
__device__ __forceinline__ void ldsm4t(uint32_t* r, uint32_t a) {
    asm volatile("ldmatrix.sync.aligned.m8n8.x4.trans.shared.b16 {%0,%1,%2,%3}, [%4];"
                 : "=r"(r[0]), "=r"(r[1]), "=r"(r[2]), "=r"(r[3]) : "r"(a));
}
__device__ __forceinline__ void mma16(float* c, const uint32_t* a, const uint32_t* b) {
    asm volatile(
        "mma.sync.aligned.m16n8k16.row.col.f32.f16.f16.f32 "
        "{%0,%1,%2,%3},{%4,%5,%6,%7},{%8,%9},{%0,%1,%2,%3};\n"
        : "+f"(c[0]), "+f"(c[1]), "+f"(c[2]), "+f"(c[3])
        : "r"(a[0]), "r"(a[1]), "r"(a[2]), "r"(a[3]),
          "r"(b[0]), "r"(b[1]));
}
__device__ __forceinline__ uint32_t packh2(float a, float b) {
    __half2 h = __floats2half2_rn(a, b);
    return *(uint32_t*)&h;
}

// ---------------------------------------------------------------------------
// Merged fp16 conversion, 4 float4 per thread (MLP=4), zero dead blocks.
// grid = (1024, 6): y=0,1 -> hs halves; y=2..5 -> weights. Every block full.
// ---------------------------------------------------------------------------
__global__ __launch_bounds__(256) void round_all(
    const float4* __restrict__ hs, const float4* __restrict__ w0,
    const float4* __restrict__ w1, const float4* __restrict__ w2,
    const float4* __restrict__ w3,
    uint2* __restrict__ ohs, uint2* __restrict__ o0, uint2* __restrict__ o1,
    uint2* __restrict__ o2, uint2* __restrict__ o3)
{
    const int y = blockIdx.y;
    const int half = (HS * HS / 4);             // 1M float4 per slab
    const float4* in;
    uint2* out;
    int off = 0;
    if (y <= 1)      { in = hs; out = ohs; off = y * half; }
    else if (y == 2) { in = w0; out = o0; }
    else if (y == 3) { in = w1; out = o1; }
    else if (y == 4) { in = w2; out = o2; }
    else             { in = w3; out = o3; }

    const int base = off + blockIdx.x * 1024 + threadIdx.x;
    float4 v[4];
#pragma unroll
    for (int i = 0; i < 4; i++) v[i] = in[base + i * 256];
#pragma unroll
    for (int i = 0; i < 4; i++) {
        uint2 o;
        o.x = packh2(v[i].x, v[i].y);
        o.y = packh2(v[i].z, v[i].w);
        out[base + i * 256] = o;
    }
}

// ---------------------------------------------------------------------------
// fp16 TN GEMM: C[M,N] = A[M,K] * B[N,K]^T      (round-12 configuration)
// Block tile 128x128, 4 warps (2x2) of 64x64, BK=64 halves, 128 threads.
// 3-stage cp.async ring (32KB/stage = 96KB) -> 2 CTAs/SM.
// Optional fused RoPE epilogue (doRope).
// ---------------------------------------------------------------------------
constexpr int GB_N      = 128;
constexpr int GH_A      = 128 * 128;          // bytes per operand per stage
constexpr int GH_STAGE  = 2 * GH_A;           // 32768
constexpr int GH_SMEM   = 3 * GH_STAGE;       // 98304
constexpr int RT_STRIDE = 68;                 // h2 per staged row (64 + pad)

template <bool OUTF>
__device__ __forceinline__ void gemm_body(
    const __half* __restrict__ A, const __half* __restrict__ B,
    void* __restrict__ Cv, int lda, int ldb, int ldc, int K, char* dsm,
    const float* __restrict__ cb, const float* __restrict__ sb, bool doRope)
{
    const uint32_t sbase = smem_u32(dsm);
    const int tid  = threadIdx.x;               // 0..127
    const int lane = tid & 31, warp = tid >> 5; // warp 0..3
    const int g = lane >> 2, tg = lane & 3;
    const int wm = (warp >> 1) * 64;            // 0 or 64
    const int wn = (warp & 1) * 64;             // 0 or 64

    const __half* Ab = A + (size_t)blockIdx.y * 128 * lda;
    const __half* Bb = B + (size_t)blockIdx.x * GB_N * ldb;

    float acc[4][8][4];
#pragma unroll
    for (int mi = 0; mi < 4; mi++)
#pragma unroll
        for (int ni = 0; ni < 8; ni++)
#pragma unroll
            for (int j = 0; j < 4; j++) acc[mi][ni][j] = 0.f;

    auto issue = [&](int s, int k0) {
        const uint32_t stA = sbase + s * GH_STAGE;
        const uint32_t stB = stA + GH_A;
#pragma unroll
        for (int i = 0; i < 8; i++) {            // A: 1024 16B units
            int idx = tid + i * 128;
            int r = idx >> 3, u = idx & 7;
            cpa16(stA + r * 128 + ((u ^ (r & 7)) << 4),
                  Ab + (size_t)r * lda + k0 + u * 8);
        }
#pragma unroll
        for (int i = 0; i < 8; i++) {            // B: 1024 16B units
            int idx = tid + i * 128;
            int r = idx >> 3, u = idx & 7;
            cpa16(stB + r * 128 + ((u ^ (r & 7)) << 4),
                  Bb + (size_t)r * ldb + k0 + u * 8);
        }
        cpa_commit();
    };

    const int nchunk = K / 64;                   // 32
    issue(0, 0); issue(1, 64);

    for (int c = 0; c < nchunk; c++) {
        cpa_wait<1>();
        __syncthreads();   // stage c ready; all warps done with stage c-1

        if (c + 2 < nchunk) issue((c + 2) % 3, (c + 2) * 64);
        else                cpa_commit();        // uniform group count

        const int s = c % 3;
        const uint32_t stA = sbase + s * GH_STAGE;
        const uint32_t stB = stA + GH_A;

#pragma unroll
        for (int ks = 0; ks < 4; ks++) {
            uint32_t af[4][4];
#pragma unroll
            for (int mi = 0; mi < 4; mi++) {
                int row = wm + 16 * mi + (lane & 15);
                int u   = 2 * ks + (lane >> 4);
                ldsm4(af[mi], stA + row * 128 + ((u ^ (row & 7)) << 4));
            }
#pragma unroll
            for (int nj = 0; nj < 4; nj++) {
                int row = wn + 16 * nj + (lane & 7) + ((lane & 16) >> 1);
                int u   = 2 * ks + ((lane >> 3) & 1);
                uint32_t t[4];
                ldsm4(t, stB + row * 128 + ((u ^ (row & 7)) << 4));
#pragma unroll
                for (int mi = 0; mi < 4; mi++) {
                    mma16(acc[mi][2 * nj],     af[mi], t);
                    mma16(acc[mi][2 * nj + 1], af[mi], t + 2);
                }
            }
        }
    }

    const size_t rbase = (size_t)blockIdx.y * 128;
    const int cbase = blockIdx.x * GB_N;

    if (OUTF) {
        float* Cf = (float*)Cv;
#pragma unroll
        for (int mi = 0; mi < 4; mi++)
#pragma unroll
            for (int ni = 0; ni < 8; ni++) {
                size_t r = rbase + wm + mi * 16 + g;
                int    cc = cbase + wn + ni * 8 + tg * 2;
                float2 v0; v0.x = acc[mi][ni][0]; v0.y = acc[mi][ni][1];
                float2 v1; v1.x = acc[mi][ni][2]; v1.y = acc[mi][ni][3];
                *(float2*)(Cf + r * ldc + cc)       = v0;
                *(float2*)(Cf + (r + 8) * ldc + cc) = v1;
            }
        return;
    }

    __half* Ch = (__half*)Cv;
    if (!doRope) {
#pragma unroll
        for (int mi = 0; mi < 4; mi++)
#pragma unroll
            for (int ni = 0; ni < 8; ni++) {
                size_t r = rbase + wm + mi * 16 + g;
                int    cc = cbase + wn + ni * 8 + tg * 2;
                *(uint32_t*)(Ch + r * ldc + cc)       = packh2(acc[mi][ni][0], acc[mi][ni][1]);
                *(uint32_t*)(Ch + (r + 8) * ldc + cc) = packh2(acc[mi][ni][2], acc[mi][ni][3]);
            }
        return;
    }

    // ---- fused RoPE epilogue (this 128-wide N tile == exactly one head) ----
    __syncthreads();                 // protect ring reads before overwrite
    uint32_t* sT = (uint32_t*)dsm;   // 128 rows x 68 h2
#pragma unroll
    for (int mi = 0; mi < 4; mi++)
#pragma unroll
        for (int ni = 0; ni < 8; ni++) {
            int r  = wm + mi * 16 + g;
            int c2 = (wn + ni * 8 + tg * 2) >> 1;
            sT[r * RT_STRIDE + c2]       = packh2(acc[mi][ni][0], acc[mi][ni][1]);
            sT[(r + 8) * RT_STRIDE + c2] = packh2(acc[mi][ni][2], acc[mi][ni][3]);
        }
    __syncthreads();

    // 128 rows x 32 h2-dims = 4096 units, 32 per thread.
    // cos[d] == cos[d+64] (concat construction) -> one float2 per pair.
#pragma unroll
    for (int i = 0; i < 32; i++) {
        int idx  = tid + i * 128;
        int d2   = idx & 31;
        int row  = idx >> 5;
        int grow = (int)rbase + row;
        int pos  = grow & (Sc - 1);
        float2 cs = *(const float2*)(cb + pos * HDc + 2 * d2);
        float2 sn = *(const float2*)(sb + pos * HDc + 2 * d2);
        uint32_t u0 = sT[row * RT_STRIDE + d2];
        uint32_t u1 = sT[row * RT_STRIDE + d2 + 32];
        __half2 h0 = *(__half2*)&u0, h1 = *(__half2*)&u1;
        float x1a = __half2float(h0.x), x1b = __half2float(h0.y);
        float x2a = __half2float(h1.x), x2b = __half2float(h1.y);
        uint32_t o0 = packh2(x1a * cs.x - x2a * sn.x, x1b * cs.y - x2b * sn.y);
        uint32_t o1 = packh2(x2a * cs.x + x1a * sn.x, x2b * cs.y + x1b * sn.y);
        int gcol = cbase + 2 * d2;
        *(uint32_t*)(Ch + (size_t)grow * ldc + gcol)      = o0;
        *(uint32_t*)(Ch + (size_t)grow * ldc + gcol + 64) = o1;
    }
}

// Merged QKV projection with fused rope on Q,K: grid = (HS/128, MR/128, 3)
__global__ __launch_bounds__(128) void gemm_qkv(
    const __half* __restrict__ A,
    const __half* __restrict__ b0, const __half* __restrict__ b1,
    const __half* __restrict__ b2,
    __half* __restrict__ c0, __half* __restrict__ c1, __half* __restrict__ c2,
    const float* __restrict__ cb, const float* __restrict__ sb)
{
    extern __shared__ char dsm[];
    const __half* B = (blockIdx.z == 0) ? b0 : (blockIdx.z == 1) ? b1 : b2;
    __half*       C = (blockIdx.z == 0) ? c0 : (blockIdx.z == 1) ? c1 : c2;
    gemm_body<false>(A, B, C, HS, HS, HS, HS, dsm, cb, sb, blockIdx.z < 2);
}

// O projection (fp32 out): grid = (HS/128, MR/128)
__global__ __launch_bounds__(128) void gemm_o(
    const __half* __restrict__ A, const __half* __restrict__ B,
    float* __restrict__ C)
{
    extern __shared__ char dsm[];
    gemm_body<true>(A, B, C, HS, HS, HS, HS, dsm, nullptr, nullptr, false);
}

// ---------------------------------------------------------------------------
// FA2-style fused causal flash attention (round-12 exact).
// 8 warps, warp w owns rows [16w, 16w+16). P in registers. K/V double-
// buffered with cross-iteration prefetch; one __syncthreads per k-tile.
// smem: Q 32K | K[2] 64K | V[2] 64K = 160 KB.
// ---------------------------------------------------------------------------
constexpr int F_Q    = 0;
constexpr int F_K0   = 32768;
constexpr int F_V0   = 98304;
constexpr int F_SMEM = 163840;

__global__ __launch_bounds__(256) void flash_h(
    const __half* __restrict__ Q, const __half* __restrict__ K,
    const __half* __restrict__ V, __half* __restrict__ O)
{
    extern __shared__ char dsm[];
    const uint32_t sbase = smem_u32(dsm);
    const uint32_t aQ = sbase + F_Q;

    const int qt = (int)gridDim.x - 1 - (int)blockIdx.x;
    const int bh = blockIdx.y;
    const int b = bh >> 4, h = bh & 15;
    const int tid  = threadIdx.x;
    const int lane = tid & 31, warp = tid >> 5;
    const int g = lane >> 2, tg = lane & 3;
    const int wr = warp * 16;

    const __half* Qb = Q + (size_t)(b * Sc + qt * 128) * HS + h * HDc;
    const __half* Kb = K + (size_t)(b * Sc) * HS + h * HDc;
    const __half* Vb = V + (size_t)(b * Sc) * HS + h * HDc;

    auto load_tile = [&](uint32_t adst, const __half* src, int ktile) {
        const __half* p = src + (size_t)(ktile * 128) * HS;
#pragma unroll
        for (int i = 0; i < 8; i++) {
            int idx = tid + i * 256;
            int r = idx >> 4, u = idx & 15;
            cpa16(adst + r * 256 + ((u ^ (r & 7)) << 4), p + (size_t)r * HS + u * 8);
        }
    };

#pragma unroll
    for (int i = 0; i < 8; i++) {
        int idx = tid + i * 256;
        int r = idx >> 4, u = idx & 15;
        cpa16(aQ + r * 256 + ((u ^ (r & 7)) << 4), Qb + (size_t)r * HS + u * 8);
    }
    load_tile(sbase + F_K0, Kb, 0);
    load_tile(sbase + F_V0, Vb, 0);
    cpa_commit();

    float acc_o[16][4];
#pragma unroll
    for (int ni = 0; ni < 16; ni++)
#pragma unroll
        for (int j = 0; j < 4; j++) acc_o[ni][j] = 0.f;
    float m0 = -1e30f, m1 = -1e30f, l0 = 0.f, l1 = 0.f;

    for (int kt = 0; kt <= qt; kt++) {
        cpa_wait<0>();
        __syncthreads();

        if (kt < qt) {
            const int nb = (kt + 1) & 1;
            load_tile(sbase + F_K0 + nb * 32768, Kb, kt + 1);
            cpa_commit();
            load_tile(sbase + F_V0 + nb * 32768, Vb, kt + 1);
            cpa_commit();
        }
        const uint32_t cK = sbase + F_K0 + (kt & 1) * 32768;
        const uint32_t cV = sbase + F_V0 + (kt & 1) * 32768;

        float accs[16][4];
#pragma unroll
        for (int ni = 0; ni < 16; ni++)
#pragma unroll
            for (int j = 0; j < 4; j++) accs[ni][j] = 0.f;

#pragma unroll
        for (int ks = 0; ks < 8; ks++) {
            uint32_t a[4];
            {
                int row = wr + (lane & 15);
                int u   = 2 * ks + (lane >> 4);
                ldsm4(a, aQ + row * 256 + ((u ^ (row & 7)) << 4));
            }
#pragma unroll
            for (int nj = 0; nj < 8; nj++) {
                int row = 16 * nj + (lane & 7) + ((lane & 16) >> 1);
                int u   = 2 * ks + ((lane >> 3) & 1);
                uint32_t t[4];
                ldsm4(t, cK + row * 256 + ((u ^ (row & 7)) << 4));
                mma16(accs[2 * nj],     a, t);
                mma16(accs[2 * nj + 1], a, t + 2);
            }
        }

        const bool diag = (kt == qt);
        const int r0 = wr + g, r1 = r0 + 8;
#pragma unroll
        for (int ni = 0; ni < 16; ni++) {
            int c0 = ni * 8 + tg * 2, c1 = c0 + 1;
            accs[ni][0] *= SCALE; accs[ni][1] *= SCALE;
            accs[ni][2] *= SCALE; accs[ni][3] *= SCALE;
            if (diag) {
                if (c0 > r0) accs[ni][0] = -1e30f;
                if (c1 > r0) accs[ni][1] = -1e30f;
                if (c0 > r1) accs[ni][2] = -1e30f;
                if (c1 > r1) accs[ni][3] = -1e30f;
            }
        }

        float lm0 = -1e30f, lm1 = -1e30f;
#pragma unroll
        for (int ni = 0; ni < 16; ni++) {
            lm0 = fmaxf(lm0, fmaxf(accs[ni][0], accs[ni][1]));
            lm1 = fmaxf(lm1, fmaxf(accs[ni][2], accs[ni][3]));
        }
        lm0 = fmaxf(lm0, __shfl_xor_sync(0xffffffffu, lm0, 1));
        lm0 = fmaxf(lm0, __shfl_xor_sync(0xffffffffu, lm0, 2));
        lm1 = fmaxf(lm1, __shfl_xor_sync(0xffffffffu, lm1, 1));
        lm1 = fmaxf(lm1, __shfl_xor_sync(0xffffffffu, lm1, 2));

        float mn0 = fmaxf(m0, lm0), mn1 = fmaxf(m1, lm1);
        float cr0 = __expf(m0 - mn0), cr1 = __expf(m1 - mn1);
        m0 = mn0; m1 = mn1;

        uint32_t ph[16][2];
        float ls0 = 0.f, ls1 = 0.f;
#pragma unroll
        for (int ni = 0; ni < 16; ni++) {
            float p0 = __expf(accs[ni][0] - mn0);
            float p1 = __expf(accs[ni][1] - mn0);
            float p2 = __expf(accs[ni][2] - mn1);
            float p3 = __expf(accs[ni][3] - mn1);
            ls0 += p0 + p1; ls1 += p2 + p3;
            ph[ni][0] = packh2(p0, p1);
            ph[ni][1] = packh2(p2, p3);
            acc_o[ni][0] *= cr0; acc_o[ni][1] *= cr0;
            acc_o[ni][2] *= cr1; acc_o[ni][3] *= cr1;
        }
        ls0 += __shfl_xor_sync(0xffffffffu, ls0, 1);
        ls0 += __shfl_xor_sync(0xffffffffu, ls0, 2);
        ls1 += __shfl_xor_sync(0xffffffffu, ls1, 1);
        ls1 += __shfl_xor_sync(0xffffffffu, ls1, 2);
        l0 = l0 * cr0 + ls0;
        l1 = l1 * cr1 + ls1;

#pragma unroll
        for (int ks = 0; ks < 8; ks++) {
            uint32_t a[4] = { ph[2 * ks][0], ph[2 * ks][1],
                              ph[2 * ks + 1][0], ph[2 * ks + 1][1] };
#pragma unroll
            for (int nj = 0; nj < 8; nj++) {
                int rowv = 16 * ks + (lane & 7) + (lane & 8);
                int u    = 2 * nj + (lane >> 4);
                uint32_t t[4];
                ldsm4t(t, cV + rowv * 256 + ((u ^ (rowv & 7)) << 4));
                mma16(acc_o[2 * nj],     a, t);
                mma16(acc_o[2 * nj + 1], a, t + 2);
            }
        }
    }

    __half* Ob = O + (size_t)(b * Sc + qt * 128) * HS + h * HDc;
    const float inv0 = 1.f / l0, inv1 = 1.f / l1;
    const int r0 = wr + g, r1 = r0 + 8;
#pragma unroll
    for (int ni = 0; ni < 16; ni++) {
        int c = ni * 8 + tg * 2;
        *(uint32_t*)(Ob + (size_t)r0 * HS + c) =
            packh2(acc_o[ni][0] * inv0, acc_o[ni][1] * inv0);
        *(uint32_t*)(Ob + (size_t)r1 * HS + c) =
            packh2(acc_o[ni][2] * inv1, acc_o[ni][3] * inv1);
    }
}

// ---------------------------------------------------------------------------
// Launcher
// ---------------------------------------------------------------------------
extern "C" void kernel_launch(void* const* d_in, const int* in_sizes, int n_in,
                              void* d_out, int out_size)
{
    const float* hs = (const float*)d_in[0];
    const float* wq = (const float*)d_in[1];
    const float* wk = (const float*)d_in[2];
    const float* wv = (const float*)d_in[3];
    const float* wo = (const float*)d_in[4];
    const float* cb = (const float*)d_in[5];
    const float* sb = (const float*)d_in[6];
    float* out = (float*)d_out;

    __half *qp, *kp, *vp, *aop, *hsp, *wqp, *wkp, *wvp, *wop;
    cudaGetSymbolAddress((void**)&qp,  g_q);
    cudaGetSymbolAddress((void**)&kp,  g_k);
    cudaGetSymbolAddress((void**)&vp,  g_v);
    cudaGetSymbolAddress((void**)&aop, g_ao);
    cudaGetSymbolAddress((void**)&hsp, g_hs);
    cudaGetSymbolAddress((void**)&wqp, g_wq);
    cudaGetSymbolAddress((void**)&wkp, g_wk);
    cudaGetSymbolAddress((void**)&wvp, g_wv);
    cudaGetSymbolAddress((void**)&wop, g_wo);

    cudaFuncSetAttribute(gemm_qkv, cudaFuncAttributeMaxDynamicSharedMemorySize, GH_SMEM);
    cudaFuncSetAttribute(gemm_o,   cudaFuncAttributeMaxDynamicSharedMemorySize, GH_SMEM);
    cudaFuncSetAttribute(flash_h,  cudaFuncAttributeMaxDynamicSharedMemorySize, F_SMEM);

    // grid (1024, 6): y=0,1 hs halves; y=2..5 weights. No dead blocks.
    round_all<<<dim3(HS * HS / 4 / 1024, 6), 256>>>(
        (const float4*)hs, (const float4*)wq, (const float4*)wk,
        (const float4*)wv, (const float4*)wo,
        (uint2*)hsp, (uint2*)wqp, (uint2*)wkp, (uint2*)wvp, (uint2*)wop);

    gemm_qkv<<<dim3(HS / GB_N, MR / 128, 3), 128, GH_SMEM>>>(
        hsp, wqp, wkp, wvp, qp, kp, vp, cb, sb);

    flash_h<<<dim3(Sc / 128, BHc), 256, F_SMEM>>>(qp, kp, vp, aop);

    gemm_o<<<dim3(HS / GB_N, MR / 128), 128, GH_SMEM>>>(aop, wop, out);
}